// round 17
// baseline (speedup 1.0000x reference)
#include <cuda_runtime.h>
#include <cstddef>
#include <cstdint>

// GRU_83133386982146: 2-layer GRU (H=10) + per-step linear 10->1.
// R17 = R16 resubmit (infra failure, not kernel): dual-batch interleave.
// Each warp runs TWO independent batch recurrences in one instruction
// stream (weights role-determined & shared; only state regs duplicate).
// Batch A's chain latency hides under batch B's instructions -> 512 warps,
// ~1 warp/SMSP. Sigmoid-side weights pre-scaled by 0.5. Combine shfls
// parked one iteration (latency hidden under FFMA2 chains).
//   lanes  0- 9: L0 unit k   (Whh0 rows . h0v), gates local
//   lanes 10-19: L1 ih dots  (Wih1 rows . h0v) -> parked in pd
//   lanes 20-29: L1 hh dots  (Whh1 rows . h1v) + L1 gates + h1 update
// smem double-buffered broadcast; h1 planes -> lin_kernel for the 10->1.

#define FULL 0xffffffffu

namespace {
constexpr int H = 10;
constexpr int T = 2048;
constexpr int B = 1024;
constexpr int NBLK = B / 2;     // 512 warps, 2 batches per warp
}

// h1 trajectory planes: [k][b*T + t]
__device__ __align__(16) float g_h1s[H][(size_t)B * T];

__device__ __forceinline__ float fast_tanh(float x) {
    float y;
    asm("tanh.approx.f32 %0, %1;" : "=f"(y) : "f"(x));
    return y;
}
__device__ __forceinline__ uint64_t pack2(float lo, float hi) {
    uint64_t r;
    asm("mov.b64 %0, {%1, %2};" : "=l"(r) : "f"(lo), "f"(hi));
    return r;
}
__device__ __forceinline__ float hadd2(uint64_t a) {
    float lo, hi;
    asm("mov.b64 {%0, %1}, %2;" : "=f"(lo), "=f"(hi) : "l"(a));
    return lo + hi;
}
__device__ __forceinline__ uint64_t ffma2(uint64_t a, uint64_t b, uint64_t c) {
    uint64_t d;
    asm("fma.rn.f32x2 %0, %1, %2, %3;" : "=l"(d) : "l"(a), "l"(b), "l"(c));
    return d;
}

__global__ void __launch_bounds__(32)
gru_warp_kernel(const float* __restrict__ x,
                const float* __restrict__ Wih0, const float* __restrict__ Whh0,
                const float* __restrict__ bih0, const float* __restrict__ bhh0,
                const float* __restrict__ Wih1, const float* __restrict__ Whh1,
                const float* __restrict__ bih1, const float* __restrict__ bhh1)
{
    const int lane = threadIdx.x;
    const int cl = (lane < 30) ? lane : 29;
    const bool isL0 = (lane < 10);
    const bool isIH = (lane >= 10 && lane < 20);
    const bool isHH = (lane >= 20);
    const int k = cl % 10;
    const int b0 = blockIdx.x * 2;
    const int b1 = b0 + 1;

    // smem: [parity][batch][40 floats]: h0 @0..9, h1 @12..21, scratch @24..39
    __shared__ __align__(16) float sbuf[2][2][40];

    const float* Wsrc = isL0 ? Whh0 : (isIH ? Wih1 : Whh1);

    // packed gate-row weights; A(=r)/B(=z) pre-scaled 0.5 (feed sigmoid)
    uint64_t wa[5], wb[5], wc[5];
#pragma unroll
    for (int j = 0; j < 5; j++) {
        wa[j] = pack2(0.5f * Wsrc[k * H + 2 * j],
                      0.5f * Wsrc[k * H + 2 * j + 1]);
        wb[j] = pack2(0.5f * Wsrc[(H + k) * H + 2 * j],
                      0.5f * Wsrc[(H + k) * H + 2 * j + 1]);
        wc[j] = pack2(Wsrc[(2 * H + k) * H + 2 * j],
                      Wsrc[(2 * H + k) * H + 2 * j + 1]);
    }
    const float cxA = isL0 ? 0.5f * Wih0[k] : 0.0f;
    const float cxB = isL0 ? 0.5f * Wih0[H + k] : 0.0f;
    const float cxC = isL0 ? Wih0[2 * H + k] : 0.0f;
    const float sA = isIH ? 0.5f * bih1[k] : 0.0f;
    const float sB = isIH ? 0.5f * bih1[H + k] : 0.0f;
    const float sC = isL0 ? bhh0[2 * H + k]
                   : (isIH ? bih1[2 * H + k] : bhh1[2 * H + k]);
    const uint64_t seedA = pack2(sA, 0.0f);
    const uint64_t seedB = pack2(sB, 0.0f);
    const uint64_t seedC = pack2(sC, 0.0f);
    const float btA = isL0 ? 0.5f * (bih0[k] + bhh0[k])
                           : (isHH ? 0.5f * bhh1[k] : 0.0f);
    const float btB = isL0 ? 0.5f * (bih0[H + k] + bhh0[H + k])
                           : (isHH ? 0.5f * bhh1[H + k] : 0.0f);
    const float btC = isL0 ? bih0[2 * H + k] : 0.0f;
    const float sel = isHH ? 1.0f : 0.0f;
    const int csrc = isHH ? (lane - 10) : lane;

    const int soff = (lane < 10) ? lane
                   : (lane < 20) ? (24 + (lane - 10))
                   : (lane < 30) ? (12 + (lane - 20))
                                 : (34 + (lane - 30));
    const int vbase = (lane < 20) ? 0 : 12;

    const float* xq0 = x + (size_t)b0 * T;
    const float* xq1 = x + (size_t)b1 * T;
    float* h1row0 = &g_h1s[k][(size_t)b0 * T];
    float* h1row1 = &g_h1s[k][(size_t)b1 * T];
    const bool hstore = (lane >= 20) && (lane < 30);

    // per-batch state
    float hownX, hownY;
    uint64_t vX[5], vY[5];
    float pAX = 0.0f, pBX = 2.0e30f, pCX = 0.0f;   // parked ih-dots, batch X
    float pAY = 0.0f, pBY = 2.0e30f, pCY = 0.0f;   // batch Y

    // ---- preamble: h0(0) for both batches (hidden dots vanish) ----
    {
        const float x00 = xq0[0];
        const float x01 = xq1[0];
        const float tA0 = fmaf(cxA, x00, btA), tA1 = fmaf(cxA, x01, btA);
        const float tB0 = fmaf(cxB, x00, btB), tB1 = fmaf(cxB, x01, btB);
        const float tC0 = fmaf(cxC, x00, btC), tC1 = fmaf(cxC, x01, btC);
        const float r0 = fmaf(fast_tanh(tA0), 0.5f, 0.5f);
        const float r1 = fmaf(fast_tanh(tA1), 0.5f, 0.5f);
        const float z0 = fmaf(fast_tanh(tB0), 0.5f, 0.5f);
        const float z1 = fmaf(fast_tanh(tB1), 0.5f, 0.5f);
        const float n0 = fast_tanh(fmaf(r0, sC, tC0));
        const float n1 = fast_tanh(fmaf(r1, sC, tC1));
        const float h00 = fmaf(z0, 0.0f - n0, n0);
        const float h01 = fmaf(z1, 0.0f - n1, n1);
        hownX = isL0 ? h00 : 0.0f;
        hownY = isL0 ? h01 : 0.0f;
#pragma unroll
        for (int j = 0; j < 5; j++) {
            const float lo0 = __shfl_sync(FULL, h00, 2 * j);
            const float hi0 = __shfl_sync(FULL, h00, 2 * j + 1);
            const float lo1 = __shfl_sync(FULL, h01, 2 * j);
            const float hi1 = __shfl_sync(FULL, h01, 2 * j + 1);
            vX[j] = (lane < 20) ? pack2(lo0, hi0) : pack2(0.0f, 0.0f);
            vY[j] = (lane < 20) ? pack2(lo1, hi1) : pack2(0.0f, 0.0f);
        }
    }

    float xcX = xq0[1], xcY = xq1[1];
    float obX[4] = {0.f, 0.f, 0.f, 0.f};
    float obY[4] = {0.f, 0.f, 0.f, 0.f};

    // Invariant (per batch): v = h0(t) lanes<20 | h1(t-2) lanes>=20;
    // hown = h0(t)_k | h1(t-2)_k; pd = ih-dots over h0(t-1).
    for (int t0 = 0; t0 < T; t0 += 4) {
#pragma unroll
        for (int u = 0; u < 4; u++) {
            const int t = t0 + u;
            // combine shfls first (operands parked last iter -> hidden)
            const float gAX = __shfl_sync(FULL, pAX, csrc);
            const float gBX = __shfl_sync(FULL, pBX, csrc);
            const float gCX = __shfl_sync(FULL, pCX, csrc);
            const float gAY = __shfl_sync(FULL, pAY, csrc);
            const float gBY = __shfl_sync(FULL, pBY, csrc);
            const float gCY = __shfl_sync(FULL, pCY, csrc);

            const int xi = (t + 2 < T) ? (t + 2) : (T - 1);
            const float xpX = xq0[xi];
            const float xpY = xq1[xi];

            // 6 packed dot chains (3 per batch), 5 FFMA2 each
            uint64_t aAX = seedA, aBX = seedB, aCX = seedC;
            uint64_t aAY = seedA, aBY = seedB, aCY = seedC;
#pragma unroll
            for (int j = 0; j < 5; j++) {
                aAX = ffma2(wa[j], vX[j], aAX);
                aAY = ffma2(wa[j], vY[j], aAY);
                aBX = ffma2(wb[j], vX[j], aBX);
                aBY = ffma2(wb[j], vY[j], aBY);
                aCX = ffma2(wc[j], vX[j], aCX);
                aCY = ffma2(wc[j], vY[j], aCY);
            }
            const float dAX = hadd2(aAX), dBX = hadd2(aBX), dCX = hadd2(aCX);
            const float dAY = hadd2(aAY), dBY = hadd2(aBY), dCY = hadd2(aCY);
            pAX = dAX; pBX = dBX; pCX = dCX;
            pAY = dAY; pBY = dBY; pCY = dCY;

            const float tAX = fmaf(cxA, xcX, btA);
            const float tBX = fmaf(cxB, xcX, btB);
            const float tCX = fmaf(cxC, xcX, btC);
            const float tAY = fmaf(cxA, xcY, btA);
            const float tBY = fmaf(cxB, xcY, btB);
            const float tCY = fmaf(cxC, xcY, btC);

            const float preAX = fmaf(sel, gAX, dAX + tAX);
            const float preBX = fmaf(sel, gBX, dBX + tBX);
            const float preAY = fmaf(sel, gAY, dAY + tAY);
            const float preBY = fmaf(sel, gBY, dBY + tBY);
            const float rX = fmaf(fast_tanh(preAX), 0.5f, 0.5f);
            const float zX = fmaf(fast_tanh(preBX), 0.5f, 0.5f);
            const float rY = fmaf(fast_tanh(preAY), 0.5f, 0.5f);
            const float zY = fmaf(fast_tanh(preBY), 0.5f, 0.5f);
            const float qX = fmaf(sel, gCX, tCX);
            const float qY = fmaf(sel, gCY, tCY);
            const float nX = fast_tanh(fmaf(rX, dCX, qX));
            const float nY = fast_tanh(fmaf(rY, dCY, qY));
            const float hnX = fmaf(zX, hownX - nX, nX);   // h0(t+1)|h1(t-1)
            const float hnY = fmaf(zY, hownY - nY, nY);
            hownX = hnX;
            hownY = hnY;

            // stage h1(t-1) circular; aligned float4 store at u==0
            obX[(u + 3) & 3] = hnX;
            obY[(u + 3) & 3] = hnY;
            if (u == 0 && t0 >= 4 && hstore) {
                *(float4*)&h1row0[t0 - 4] = make_float4(obX[0], obX[1], obX[2], obX[3]);
                *(float4*)&h1row1[t0 - 4] = make_float4(obY[0], obY[1], obY[2], obY[3]);
            }

            // broadcast both batches, ONE syncwarp
            const int p = u & 1;
            sbuf[p][0][soff] = hnX;
            sbuf[p][1][soff] = hnY;
            __syncwarp();
            {
                const ulonglong2 A0 = *(const ulonglong2*)&sbuf[p][0][vbase];
                const ulonglong2 A1 = *(const ulonglong2*)&sbuf[p][0][vbase + 4];
                vX[0] = A0.x; vX[1] = A0.y; vX[2] = A1.x; vX[3] = A1.y;
                vX[4] = *(const uint64_t*)&sbuf[p][0][vbase + 8];
                const ulonglong2 B0 = *(const ulonglong2*)&sbuf[p][1][vbase];
                const ulonglong2 B1 = *(const ulonglong2*)&sbuf[p][1][vbase + 4];
                vY[0] = B0.x; vY[1] = B0.y; vY[2] = B1.x; vY[3] = B1.y;
                vY[4] = *(const uint64_t*)&sbuf[p][1][vbase + 8];
            }

            xcX = xpX;
            xcY = xpY;
        }
    }

    // ---- epilogue: one more HH half-step per batch -> h1(T-1) ----
    {
        const float gAX = __shfl_sync(FULL, pAX, csrc);
        const float gBX = __shfl_sync(FULL, pBX, csrc);
        const float gCX = __shfl_sync(FULL, pCX, csrc);
        const float gAY = __shfl_sync(FULL, pAY, csrc);
        const float gBY = __shfl_sync(FULL, pBY, csrc);
        const float gCY = __shfl_sync(FULL, pCY, csrc);
        uint64_t aAX = seedA, aBX = seedB, aCX = seedC;
        uint64_t aAY = seedA, aBY = seedB, aCY = seedC;
#pragma unroll
        for (int j = 0; j < 5; j++) {
            aAX = ffma2(wa[j], vX[j], aAX);
            aAY = ffma2(wa[j], vY[j], aAY);
            aBX = ffma2(wb[j], vX[j], aBX);
            aBY = ffma2(wb[j], vY[j], aBY);
            aCX = ffma2(wc[j], vX[j], aCX);
            aCY = ffma2(wc[j], vY[j], aCY);
        }
        const float dAX = hadd2(aAX), dBX = hadd2(aBX), dCX = hadd2(aCX);
        const float dAY = hadd2(aAY), dBY = hadd2(aBY), dCY = hadd2(aCY);
        const float preAX = fmaf(sel, gAX, dAX + btA);
        const float preBX = fmaf(sel, gBX, dBX + btB);
        const float preAY = fmaf(sel, gAY, dAY + btA);
        const float preBY = fmaf(sel, gBY, dBY + btB);
        const float rX = fmaf(fast_tanh(preAX), 0.5f, 0.5f);
        const float zX = fmaf(fast_tanh(preBX), 0.5f, 0.5f);
        const float rY = fmaf(fast_tanh(preAY), 0.5f, 0.5f);
        const float zY = fmaf(fast_tanh(preBY), 0.5f, 0.5f);
        const float qX = fmaf(sel, gCX, btC);
        const float qY = fmaf(sel, gCY, btC);
        const float nX = fast_tanh(fmaf(rX, dCX, qX));
        const float nY = fast_tanh(fmaf(rY, dCY, qY));
        const float hnX = fmaf(zX, hownX - nX, nX);
        const float hnY = fmaf(zY, hownY - nY, nY);
        obX[3] = hnX;
        obY[3] = hnY;
        if (hstore) {
            *(float4*)&h1row0[T - 4] = make_float4(obX[0], obX[1], obX[2], obX[3]);
            *(float4*)&h1row1[T - 4] = make_float4(obY[0], obY[1], obY[2], obY[3]);
        }
    }
}

__global__ void __launch_bounds__(256)
lin_kernel(const float* __restrict__ Wlin, const float* __restrict__ blin,
           float* __restrict__ out)
{
    const int i4 = (blockIdx.x * blockDim.x + threadIdx.x) * 4;
    if (i4 >= B * T) return;
    const float bl = blin[0];
    float a0 = bl, a1 = bl, a2 = bl, a3 = bl;
#pragma unroll
    for (int k = 0; k < H; k++) {
        const float w = Wlin[k];
        const float4 h = *(const float4*)&g_h1s[k][i4];
        a0 = fmaf(w, h.x, a0);
        a1 = fmaf(w, h.y, a1);
        a2 = fmaf(w, h.z, a2);
        a3 = fmaf(w, h.w, a3);
    }
    *(float4*)&out[i4] = make_float4(a0, a1, a2, a3);
}

extern "C" void kernel_launch(void* const* d_in, const int* in_sizes, int n_in,
                              void* d_out, int out_size) {
    (void)in_sizes; (void)n_in; (void)out_size;
    const float* x    = (const float*)d_in[0];
    const float* Wih0 = (const float*)d_in[1];
    const float* Whh0 = (const float*)d_in[2];
    const float* bih0 = (const float*)d_in[3];
    const float* bhh0 = (const float*)d_in[4];
    const float* Wih1 = (const float*)d_in[5];
    const float* Whh1 = (const float*)d_in[6];
    const float* bih1 = (const float*)d_in[7];
    const float* bhh1 = (const float*)d_in[8];
    const float* Wlin = (const float*)d_in[9];
    const float* blin = (const float*)d_in[10];
    float* out = (float*)d_out;

    gru_warp_kernel<<<NBLK, 32>>>(x, Wih0, Whh0, bih0, bhh0,
                                  Wih1, Whh1, bih1, bhh1);
    lin_kernel<<<(B * T / 4 + 255) / 256, 256>>>(Wlin, blin, out);
}